// round 15
// baseline (speedup 1.0000x reference)
#include <cuda_runtime.h>
#include <cstdint>

// ---------------- problem constants ----------------
#define BATCH   2
#define NPTS    110592            // 48^3
#define BN      (BATCH * NPTS)    // 221184
#define NF      256
#define NM      16
#define NCHUNK  432               // chunks per batch
#define CHUNK   256               // points per CTA (432 * 256 = 110592)
#define NPB     (CHUNK / 8)       // 32 point-blocks of 8
#define TWO_PI_F 6.283185307179586f
#define INV_SQRT_N 0.0030070286f  // 1/sqrt(110592)

#define NOUT       (BATCH * NF * NM)       // 8192 complex elements
#define OUT_FLOATS (NOUT * 2)              // 16384

// reduction tree: 432 = 27 * 16
#define R1_GROUPS  27
#define R1_CH      16

#define SZ_A   (BN * 16)
#define SZ_X   (BN * 3)
#define SZ_AW  (16 * 16)
#define SZ_XW  (3 * 256)

// SMEM layout (floats): aw[256] | xraw[768] | x4[1024] | A[4096]
#define SMF_AW  0
#define SMF_XR  256
#define SMF_X4  (256 + 768)
#define SMF_A   (256 + 768 + 1024)
#define SMEM_BYTES ((256 + 768 + 1024 + 4096) * 4)   // 24576

// ---------------- device scratch (no allocation allowed) ----------------
__device__ float g_part[NCHUNK * OUT_FLOATS];     // per-chunk planar partials (28.3 MB)
__device__ float g_p2[R1_GROUPS * OUT_FLOATS];    // stage-1 partials (1.8 MB)

// ---------------- helpers ----------------
__device__ __forceinline__ uint32_t tf32r(float f) {
    uint32_t r;
    asm("cvt.rna.tf32.f32 %0, %1;" : "=r"(r) : "f"(f));
    return r;
}
__device__ __forceinline__ void mma_tf32(float* d, const uint32_t* a, const uint32_t* b) {
    asm volatile(
        "mma.sync.aligned.m16n8k8.row.col.f32.tf32.tf32.f32 "
        "{%0,%1,%2,%3}, {%4,%5,%6,%7}, {%8,%9}, {%0,%1,%2,%3};"
        : "+f"(d[0]), "+f"(d[1]), "+f"(d[2]), "+f"(d[3])
        : "r"(a[0]), "r"(a[1]), "r"(a[2]), "r"(a[3]), "r"(b[0]), "r"(b[1]));
}

// ---------- fused kernel: stage + project + sincos + tf32 MMA ----------
// grid = (NCHUNK, BATCH), 256 threads; warp w covers f in [w*32, w*32+32).
// s_A columns XOR-swizzled: A[p][m] stored at col (m + 8*((p>>1)&1)) & 15
// -> B-operand LDS are bank-conflict-free.
__global__ void __launch_bounds__(256, 3) spectral_main(const float* __restrict__ a,
                                                        const float* __restrict__ x,
                                                        const float* __restrict__ aw,
                                                        const float* __restrict__ xw) {
    extern __shared__ float sm[];
    float*  s_aw = sm + SMF_AW;             // 16x16 row-major [i][m]
    float*  s_xr = sm + SMF_XR;             // 256 x 3 raw
    float4* s_x4 = (float4*)(sm + SMF_X4);  // 256 x float4 (padded)
    float*  s_A  = sm + SMF_A;              // 256 x 16, col-swizzled tf32 coefficients

    const int tid  = threadIdx.x;
    const int lane = tid & 31;
    const int warp = tid >> 5;
    const int b    = blockIdx.y;
    const int chunk = blockIdx.x;
    const size_t pbase = (size_t)(b * NPTS + chunk * CHUNK);

    // ---- stage: aw, raw a-chunk (16KB), raw x-chunk (3KB), all coalesced ----
    s_aw[tid] = aw[tid];
    {
        const float4* ga = (const float4*)(a + pbase * 16);   // 1024 float4
        float4* sa4 = (float4*)s_A;
#pragma unroll
        for (int i = 0; i < 4; ++i) sa4[tid + 256 * i] = ga[tid + 256 * i];
        const float4* gx = (const float4*)(x + pbase * 3);    // 192 float4
        float4* sx4 = (float4*)s_xr;
        if (tid < 192) sx4[tid] = gx[tid];
    }
    __syncthreads();

    // ---- pad x to float4: one point per thread ----
    {
        float r0 = s_xr[tid * 3 + 0], r1 = s_xr[tid * 3 + 1], r2 = s_xr[tid * 3 + 2];
        s_x4[tid] = make_float4(r0, r1, r2, 0.0f);
    }

    // ---- in-place projection (reads raw row, writes swizzled row) ----
    {
        int p = tid;
        const int swp = ((p >> 1) & 1) * 8;   // column swizzle for this row
        float ai[16];
#pragma unroll
        for (int i = 0; i < 16; ++i) ai[i] = s_A[p * 16 + i];
        float o[16];
#pragma unroll
        for (int m = 0; m < 16; ++m) o[m] = 0.0f;
#pragma unroll
        for (int i = 0; i < 16; ++i)
#pragma unroll
            for (int m = 0; m < 16; ++m)
                o[m] = fmaf(ai[i], s_aw[i * 16 + m], o[m]);
#pragma unroll
        for (int m = 0; m < 16; ++m)
            s_A[p * 16 + ((m + swp) & 15)] = __uint_as_float(tf32r(o[m] * INV_SQRT_N));
    }
    __syncthreads();

    // ---- per-thread frequency weights (2*pi folded), 4 f's per thread ----
    const int fb = warp * 32 + (lane >> 2);
    float W[4][3];
#pragma unroll
    for (int j = 0; j < 4; ++j) {
        int f = fb + 8 * j;
        W[j][0] = TWO_PI_F * xw[f];
        W[j][1] = TWO_PI_F * xw[NF + f];
        W[j][2] = TWO_PI_F * xw[2 * NF + f];
    }

    float accR[2][2][4], accI[2][2][4];
#pragma unroll
    for (int i = 0; i < 2; ++i)
#pragma unroll
        for (int j = 0; j < 2; ++j)
#pragma unroll
            for (int k = 0; k < 4; ++k) { accR[i][j][k] = 0.0f; accI[i][j][k] = 0.0f; }

    const int kp = lane & 3;        // k-position within point-block
    const int m0 = lane >> 2;       // m channel for B fragment
    // swizzled columns for this thread's B loads ((kp>>1)&1 == (p0>>1)&1, pb-invariant)
    const int c0 = (m0 + (((lane >> 1) & 1) * 8)) & 15;
    const int c8 = c0 ^ 8;

    // prefetch first x pair
    float4 xv0 = s_x4[kp];
    float4 xv1 = s_x4[kp + 4];

    for (int pb = 0; pb < NPB; ++pb) {
        const int p0 = pb * 8 + kp;

        // prefetch next pb's x (dead-safe index for last iter)
        const int np = ((pb + 1) & (NPB - 1)) * 8 + kp;
        float4 nx0 = s_x4[np];
        float4 nx1 = s_x4[np + 4];

        float cv[8], sv[8];             // [j*2 + psel]
#pragma unroll
        for (int j = 0; j < 4; ++j) {
            float ph0 = fmaf(xv0.x, W[j][0], fmaf(xv0.y, W[j][1], xv0.z * W[j][2]));
            float ph1 = fmaf(xv1.x, W[j][0], fmaf(xv1.y, W[j][1], xv1.z * W[j][2]));
            __sincosf(ph0, &sv[2 * j], &cv[2 * j]);
            __sincosf(ph1, &sv[2 * j + 1], &cv[2 * j + 1]);
        }

        // A fragments: raw fp32 bits (tf32 MMA HW truncates low mantissa bits)
        uint32_t fc0[4] = { __float_as_uint(cv[0]), __float_as_uint(cv[2]),
                            __float_as_uint(cv[1]), __float_as_uint(cv[3]) };
        uint32_t fs0[4] = { __float_as_uint(sv[0]), __float_as_uint(sv[2]),
                            __float_as_uint(sv[1]), __float_as_uint(sv[3]) };
        uint32_t fc1[4] = { __float_as_uint(cv[4]), __float_as_uint(cv[6]),
                            __float_as_uint(cv[5]), __float_as_uint(cv[7]) };
        uint32_t fs1[4] = { __float_as_uint(sv[4]), __float_as_uint(sv[6]),
                            __float_as_uint(sv[5]), __float_as_uint(sv[7]) };

        // B fragments via swizzled, conflict-free LDS
        uint32_t bm0[2] = { __float_as_uint(s_A[p0 * 16 + c0]),
                            __float_as_uint(s_A[(p0 + 4) * 16 + c0]) };
        uint32_t bm8[2] = { __float_as_uint(s_A[p0 * 16 + c8]),
                            __float_as_uint(s_A[(p0 + 4) * 16 + c8]) };

        mma_tf32(accR[0][0], fc0, bm0);  mma_tf32(accR[0][1], fc0, bm8);
        mma_tf32(accI[0][0], fs0, bm0);  mma_tf32(accI[0][1], fs0, bm8);
        mma_tf32(accR[1][0], fc1, bm0);  mma_tf32(accR[1][1], fc1, bm8);
        mma_tf32(accI[1][0], fs1, bm0);  mma_tf32(accI[1][1], fs1, bm8);

        xv0 = nx0;
        xv1 = nx1;
    }

    // ---- epilogue: C-fragment -> planar per-chunk partials ----
    float* basep = g_part + (size_t)chunk * OUT_FLOATS;
#pragma unroll
    for (int ft = 0; ft < 2; ++ft) {
#pragma unroll
        for (int mh = 0; mh < 2; ++mh) {
            int mcol = mh * 8 + 2 * kp;
#pragma unroll
            for (int rh = 0; rh < 2; ++rh) {
                int f = warp * 32 + ft * 16 + (lane >> 2) + rh * 8;
                size_t o = (size_t)(b * NF + f) * NM + mcol;
                float2 vr = make_float2(accR[ft][mh][2 * rh], accR[ft][mh][2 * rh + 1]);
                float2 vi = make_float2(-accI[ft][mh][2 * rh], -accI[ft][mh][2 * rh + 1]);
                *(float2*)(basep + o) = vr;              // real plane
                *(float2*)(basep + NOUT + o) = vi;       // imag plane
            }
        }
    }
}

// ---------- reduce stage 1: sum 16 chunks per group ----------
__global__ void __launch_bounds__(256) reduce1_kernel(void) {
    int j = blockIdx.x * 256 + threadIdx.x;
    int c0 = blockIdx.y * R1_CH;
    float s = 0.0f;
#pragma unroll
    for (int c = 0; c < R1_CH; ++c)
        s += g_part[(size_t)(c0 + c) * OUT_FLOATS + j];
    g_p2[(size_t)blockIdx.y * OUT_FLOATS + j] = s;
}

// ---------- reduce stage 2: sum 27 groups, write planar output ----------
__global__ void __launch_bounds__(256) reduce2_kernel(float* __restrict__ out, int write_imag) {
    int j = blockIdx.x * 256 + threadIdx.x;
    float s = 0.0f;
#pragma unroll
    for (int g = 0; g < R1_GROUPS; ++g)
        s += g_p2[(size_t)g * OUT_FLOATS + j];
    if (j < NOUT) out[j] = s;
    else if (write_imag) out[j] = s;
}

extern "C" void kernel_launch(void* const* d_in, const int* in_sizes, int n_in,
                              void* d_out, int out_size) {
    const float* a  = nullptr;
    const float* x  = nullptr;
    const float* aw = nullptr;
    const float* xw = nullptr;
    for (int i = 0; i < n_in; ++i) {
        switch (in_sizes[i]) {
            case SZ_A:  a  = (const float*)d_in[i]; break;
            case SZ_X:  x  = (const float*)d_in[i]; break;
            case SZ_AW: aw = (const float*)d_in[i]; break;
            case SZ_XW: xw = (const float*)d_in[i]; break;
            default: break;
        }
    }
    float* out = (float*)d_out;
    int write_imag = (out_size >= OUT_FLOATS) ? 1 : 0;

    cudaFuncSetAttribute(spectral_main,
                         cudaFuncAttributeMaxDynamicSharedMemorySize, SMEM_BYTES);

    dim3 grid(NCHUNK, BATCH);
    spectral_main<<<grid, 256, SMEM_BYTES>>>(a, x, aw, xw);
    dim3 rg1(OUT_FLOATS / 256, R1_GROUPS);
    reduce1_kernel<<<rg1, 256>>>();
    reduce2_kernel<<<OUT_FLOATS / 256, 256>>>(out, write_imag);
}